// round 1
// baseline (speedup 1.0000x reference)
#include <cuda_runtime.h>
#include <cuda_bf16.h>

#define TS_X 32
#define TS_Y 8
#define HALO 3
#define TILE_W (TS_X + 2 * HALO)   // 38
#define TILE_H (TS_Y + 2 * HALO)   // 14
#define TILE_ELEMS (TILE_W * TILE_H)

__device__ __forceinline__ bool det9(unsigned b) {
    // 24-bit circular buffer: b | (low 8 bits << 16); 9-consecutive-ones
    // via run-length folding. Bit i of result set <=> bits i..i+8 all set.
    unsigned v = b | ((b & 0xFFu) << 16);
    v &= v >> 1;   // runs >= 2
    v &= v >> 2;   // runs >= 4
    v &= v >> 4;   // runs >= 8
    v &= v >> 1;   // runs >= 9
    return (v & 0xFFFFu) != 0u;
}

__global__ __launch_bounds__(TS_X * TS_Y)
void fast_score_kernel(const float* __restrict__ img,
                       float* __restrict__ out,
                       int H, int W) {
    __shared__ float s[TILE_H][TILE_W];

    const int n = blockIdx.z;
    const float* im = img + (size_t)n * H * W;
    float* om = out + (size_t)n * H * W;

    const int bx = blockIdx.x * TS_X;
    const int by = blockIdx.y * TS_Y;
    const int tid = threadIdx.y * TS_X + threadIdx.x;

    // Cooperative tile fill with replicate clamp at image borders.
    #pragma unroll
    for (int i = tid; i < TILE_ELEMS; i += TS_X * TS_Y) {
        int ly = i / TILE_W;
        int lx = i - ly * TILE_W;
        int gy = by + ly - HALO;
        int gx = bx + lx - HALO;
        gy = min(max(gy, 0), H - 1);
        gx = min(max(gx, 0), W - 1);
        s[ly][lx] = __ldg(&im[(size_t)gy * W + gx]);
    }
    __syncthreads();

    const int x = bx + threadIdx.x;
    const int y = by + threadIdx.y;
    if (x >= W || y >= H) return;

    const int lx = threadIdx.x + HALO;
    const int ly = threadIdx.y + HALO;
    const float c = s[ly][lx];

    unsigned dark = 0u, bright = 0u;

    // Same op order as reference: d = circle - center; d >= 20 / d <= -20.
    #define CK(j, dy, dx) {                                   \
        float d = s[ly + (dy)][lx + (dx)] - c;                \
        dark   |= ((unsigned)(d >=  20.0f)) << (j);           \
        bright |= ((unsigned)(d <= -20.0f)) << (j);           \
    }
    CK( 0,  0, -3)  CK( 1,  1, -3)  CK( 2,  2, -2)  CK( 3,  3, -1)
    CK( 4,  3,  0)  CK( 5,  3,  1)  CK( 6,  2,  2)  CK( 7,  1,  3)
    CK( 8,  0,  3)  CK( 9, -1,  3)  CK(10, -2,  2)  CK(11, -3,  1)
    CK(12, -3,  0)  CK(13, -3, -1)  CK(14, -2, -2)  CK(15, -1, -3)
    #undef CK

    bool detected = det9(dark) || det9(bright);
    om[(size_t)y * W + x] = detected ? 1.0f : 0.0f;
}

extern "C" void kernel_launch(void* const* d_in, const int* in_sizes, int n_in,
                              void* d_out, int out_size) {
    const float* img = (const float*)d_in[0];
    float* out = (float*)d_out;

    const int H = 1080;
    const int W = 1920;
    const int N = in_sizes[0] / (H * W);

    dim3 block(TS_X, TS_Y, 1);
    dim3 grid((W + TS_X - 1) / TS_X, (H + TS_Y - 1) / TS_Y, N);
    fast_score_kernel<<<grid, block>>>(img, out, H, W);
}

// round 2
// speedup vs baseline: 1.4712x; 1.4712x over previous
#include <cuda_runtime.h>
#include <cuda_bf16.h>

#define BX 32
#define BY 8
#define PY 2                        // pixels per thread (vertical, strided by BY)
#define TPY (BY * PY)               // 16 pixel rows per block
#define HALO 3
#define TW (BX + 2 * HALO)          // 38
#define TH (TPY + 2 * HALO)         // 22
#define TILE_ELEMS (TW * TH)        // 836
#define NTHREADS (BX * BY)          // 256

__device__ __forceinline__ unsigned fold9(unsigned b) {
    // 24-bit circular buffer: bytes [b0, b1, b0, 0]. Bit i of result set
    // <=> 9 consecutive set bits starting at rotation i. Bits >= 16 of the
    // result are automatically 0 (they include zero bits >= 24), so no mask.
    unsigned v = __byte_perm(b, 0, 0x4010);
    v &= v >> 1;   // runs >= 2
    v &= v >> 2;   // runs >= 4
    v &= v >> 4;   // runs >= 8
    v &= v >> 1;   // runs >= 9
    return v;
}

__global__ __launch_bounds__(NTHREADS)
void fast_score_kernel(const float* __restrict__ img,
                       float* __restrict__ out,
                       int H, int W) {
    __shared__ float sm[TILE_ELEMS];

    const int n = blockIdx.z;
    const float* im = img + (size_t)n * H * W;
    float* om = out + (size_t)n * H * W;

    const int bx = blockIdx.x * BX;
    const int by = blockIdx.y * TPY;
    const int tid = threadIdx.y * BX + threadIdx.x;

    // Interior test is uniform per block: no clamping, no store guard needed.
    const bool interior = (blockIdx.x > 0) & (blockIdx.x < gridDim.x - 1) &
                          (blockIdx.y > 0) & (by + TH - HALO <= H);

    if (interior) {
        const float* base = im + (size_t)(by - HALO) * W + (bx - HALO);
        #pragma unroll
        for (int k = 0; k < 4; k++) {
            int i = tid + k * NTHREADS;
            if (i < TILE_ELEMS) {
                int ly = i / TW;
                int lx = i - ly * TW;
                sm[i] = __ldg(base + (size_t)ly * W + lx);
            }
        }
    } else {
        #pragma unroll
        for (int k = 0; k < 4; k++) {
            int i = tid + k * NTHREADS;
            if (i < TILE_ELEMS) {
                int ly = i / TW;
                int lx = i - ly * TW;
                int gy = min(max(by + ly - HALO, 0), H - 1);
                int gx = min(max(bx + lx - HALO, 0), W - 1);
                sm[i] = __ldg(&im[(size_t)gy * W + gx]);
            }
        }
    }
    __syncthreads();

    const int lx = threadIdx.x + HALO;
    const int x = bx + threadIdx.x;

    #pragma unroll
    for (int p = 0; p < PY; p++) {
        const int py = threadIdx.y + p * BY;  // pixel row within block tile
        const int ly = py + HALO;
        const float c = sm[ly * TW + lx];

        unsigned dark = 0u, bright = 0u;

        // Same op order as reference: d = circle - center; d >= 20 / d <= -20.
        #define CK(j, dy, dx) {                                   \
            float d = sm[(ly + (dy)) * TW + (lx + (dx))] - c;     \
            if (d >=  20.0f) dark   |= (1u << (j));               \
            if (d <= -20.0f) bright |= (1u << (j));               \
        }
        CK( 0,  0, -3)  CK( 1,  1, -3)  CK( 2,  2, -2)  CK( 3,  3, -1)
        CK( 4,  3,  0)  CK( 5,  3,  1)  CK( 6,  2,  2)  CK( 7,  1,  3)
        CK( 8,  0,  3)  CK( 9, -1,  3)  CK(10, -2,  2)  CK(11, -3,  1)
        CK(12, -3,  0)  CK(13, -3, -1)  CK(14, -2, -2)  CK(15, -1, -3)
        #undef CK

        float r = (fold9(dark) | fold9(bright)) ? 1.0f : 0.0f;

        const int y = by + py;
        if (interior) {
            om[(size_t)y * W + x] = r;
        } else if (y < H) {        // x < W always (W % BX == 0)
            om[(size_t)y * W + x] = r;
        }
    }
}

extern "C" void kernel_launch(void* const* d_in, const int* in_sizes, int n_in,
                              void* d_out, int out_size) {
    const float* img = (const float*)d_in[0];
    float* out = (float*)d_out;

    const int H = 1080;
    const int W = 1920;
    const int N = in_sizes[0] / (H * W);

    dim3 block(BX, BY, 1);
    dim3 grid((W + BX - 1) / BX, (H + TPY - 1) / TPY, N);
    fast_score_kernel<<<grid, block>>>(img, out, H, W);
}

// round 3
// speedup vs baseline: 1.9507x; 1.3259x over previous
#include <cuda_runtime.h>
#include <cuda_bf16.h>

#define IW 1920
#define IH 1080
#define BXT 32            // threads x
#define BYT 8             // threads y
#define PXW 4             // horizontal pixels per thread
#define TPW (BXT * PXW)   // 128 pixel-wide tile
#define SMW 136           // floats per smem row: 4 pad + 128 + 4 pad
#define SMH 14            // 8 rows + 2*3 halo
#define NF4 ((SMW / 4) * SMH)  // 34 * 14 = 476
#define NTH (BXT * BYT)   // 256

__device__ __forceinline__ unsigned fold9(unsigned b) {
    // 24-bit circular buffer = bytes [b0, b1, b0, 0] via one PRMT.
    // Run-length fold: result bit i set <=> bits i..i+8 all set.
    // Bits >= 16 of the result are automatically 0 (byte3 == 0).
    unsigned v = __byte_perm(b, 0, 0x4010);
    v &= v >> 1;   // runs >= 2
    v &= v >> 2;   // runs >= 4
    v &= v >> 4;   // runs >= 8
    v &= v >> 1;   // runs >= 9
    return v;
}

__global__ __launch_bounds__(NTH)
void fast_score_kernel(const float* __restrict__ img,
                       float* __restrict__ out) {
    __shared__ __align__(16) float sm[SMH * SMW];

    const int n = blockIdx.z;
    const float* im = img + (size_t)n * (IH * IW);
    float* om = out + (size_t)n * (IH * IW);

    const int bx = blockIdx.x * TPW;
    const int by = blockIdx.y * BYT;
    const int tid = threadIdx.y * BXT + threadIdx.x;

    const bool interior = (blockIdx.x > 0) & (blockIdx.x < gridDim.x - 1) &
                          (blockIdx.y > 0) & (blockIdx.y < gridDim.y - 1);

    if (interior) {
        // Tile covers rows by-3..by+10, cols bx-4..bx+131, all in-bounds,
        // 16B-aligned (bx % 128 == 0). Pure LDG.128/STS.128 fill.
        const float4* g = (const float4*)(im + (size_t)(by - 3) * IW + (bx - 4));
        #pragma unroll
        for (int k = 0; k < 2; k++) {
            int i = tid + k * NTH;
            if (i < NF4) {
                int ly = i / 34;
                int kx = i - ly * 34;
                ((float4*)sm)[i] = g[ly * (IW / 4) + kx];
            }
        }
    } else {
        // Boundary blocks: scalar fill with replicate clamp.
        #pragma unroll
        for (int k = 0; k < 8; k++) {
            int e = tid + k * NTH;
            if (e < SMH * SMW) {
                int ly = e / SMW;
                int lx = e - ly * SMW;
                int gy = min(max(by + ly - 3, 0), IH - 1);
                int gx = min(max(bx + lx - 4, 0), IW - 1);
                sm[e] = __ldg(&im[(size_t)gy * IW + gx]);
            }
        }
    }
    __syncthreads();

    // Pixel i of this thread: x0+i, x0 = bx + tx*4. smem col of x0 is tx*4+4.
    // w[j] (after LOADROW) = value at column x0 + j - 4 of that row.
    const int basei = (threadIdx.y + 3) * SMW + threadIdx.x * 4 + 4;

    float w[12], c[4];
    unsigned dk[4] = {0u, 0u, 0u, 0u};
    unsigned br[4] = {0u, 0u, 0u, 0u};

    #define LOADROW(dy) {                                                   \
        const float4* p = (const float4*)(sm + basei + (dy) * SMW - 4);     \
        float4 A = p[0], B = p[1], C = p[2];                                \
        w[0]=A.x; w[1]=A.y; w[2]=A.z;  w[3]=A.w;                            \
        w[4]=B.x; w[5]=B.y; w[6]=B.z;  w[7]=B.w;                            \
        w[8]=C.x; w[9]=C.y; w[10]=C.z; w[11]=C.w; }

    // Same op order as reference: d = circle - center; d>=20 / d<=-20.
    #define CMP(i, dx, bit) {                                               \
        float d = w[(i) + 4 + (dx)] - c[i];                                 \
        if (d >=  20.0f) dk[i] |= (1u << (bit));                            \
        if (d <= -20.0f) br[i] |= (1u << (bit)); }

    #define ROW2(dxa, ba, dxb, bb)                                          \
        _Pragma("unroll") for (int i = 0; i < 4; i++) {                     \
            CMP(i, dxa, ba) CMP(i, dxb, bb) }
    #define ROW3(dxa, ba, dxb, bb, dxc, bc)                                 \
        _Pragma("unroll") for (int i = 0; i < 4; i++) {                     \
            CMP(i, dxa, ba) CMP(i, dxb, bb) CMP(i, dxc, bc) }

    LOADROW(0);
    c[0] = w[4]; c[1] = w[5]; c[2] = w[6]; c[3] = w[7];
    ROW2(-3, 0,  3, 8);                     // (0,-3)->0, (0,3)->8
    LOADROW(-3); ROW3(-1, 13, 0, 12, 1, 11);
    LOADROW(-2); ROW2(-2, 14, 2, 10);
    LOADROW(-1); ROW2(-3, 15, 3,  9);
    LOADROW( 1); ROW2(-3,  1, 3,  7);
    LOADROW( 2); ROW2(-2,  2, 2,  6);
    LOADROW( 3); ROW3(-1,  3, 0,  4, 1, 5);

    #undef LOADROW
    #undef CMP
    #undef ROW2
    #undef ROW3

    float4 r;
    r.x = (fold9(dk[0]) | fold9(br[0])) ? 1.0f : 0.0f;
    r.y = (fold9(dk[1]) | fold9(br[1])) ? 1.0f : 0.0f;
    r.z = (fold9(dk[2]) | fold9(br[2])) ? 1.0f : 0.0f;
    r.w = (fold9(dk[3]) | fold9(br[3])) ? 1.0f : 0.0f;

    const int y = by + threadIdx.y;
    *(float4*)(om + (size_t)y * IW + bx + threadIdx.x * 4) = r;
}

extern "C" void kernel_launch(void* const* d_in, const int* in_sizes, int n_in,
                              void* d_out, int out_size) {
    const float* img = (const float*)d_in[0];
    float* out = (float*)d_out;
    const int N = in_sizes[0] / (IH * IW);

    dim3 block(BXT, BYT, 1);
    dim3 grid(IW / TPW, IH / BYT, N);   // 15 x 135 x N (exact)
    fast_score_kernel<<<grid, block>>>(img, out);
}